// round 1
// baseline (speedup 1.0000x reference)
#include <cuda_runtime.h>
#include <math.h>
#include <float.h>

#define BB   8
#define CC   192
#define OUTC 384
#define NN   3136          // 56*56
#define KNN  16
#define MTOT (BB*NN)       // 25088
#define EPSV 1e-5f

// ---------------- scratch (device globals; no runtime allocation) ----------
__device__ float g_xf[(size_t)BB*NN*CC];          // (b, n, c)  19.3 MB
__device__ float g_x2[MTOT];                      // row squared norms
__device__ float g_s[(size_t)BB*NN*NN];           // s[b][i][j] = x2[j]-2*inner  315 MB
__device__ float g_feat[(size_t)MTOT*2*CC];       // interleaved (x, maxrel)  38.5 MB
__device__ float g_z[(size_t)OUTC*MTOT];          // z[o][m] pre-BN            38.5 MB
__device__ float g_scale[OUTC];
__device__ float g_shift[OUTC];

// ---------------- 1) transpose (B,C,N) -> (B,N,C) ---------------------------
__global__ void transpose_kernel(const float* __restrict__ x) {
    __shared__ float tile[32][33];
    int b  = blockIdx.z;
    int c0 = blockIdx.y * 32;
    int n0 = blockIdx.x * 32;
    int tx = threadIdx.x, ty = threadIdx.y;   // 32 x 8
    #pragma unroll
    for (int i = ty; i < 32; i += 8)
        tile[i][tx] = x[((size_t)b*CC + (c0+i))*NN + n0 + tx];
    __syncthreads();
    #pragma unroll
    for (int i = ty; i < 32; i += 8)
        g_xf[((size_t)b*NN + (n0+i))*CC + c0 + tx] = tile[tx][i];
}

// ---------------- 2) squared norms ------------------------------------------
__global__ void x2_kernel() {
    int row = blockIdx.x * 8 + threadIdx.y;   // MTOT = 3136*8 exact
    const float* p = g_xf + (size_t)row * CC;
    float s = 0.f;
    for (int c = threadIdx.x; c < CC; c += 32) { float v = p[c]; s += v*v; }
    #pragma unroll
    for (int o = 16; o; o >>= 1) s += __shfl_xor_sync(0xffffffffu, s, o);
    if (threadIdx.x == 0) g_x2[row] = s;
}

// ---------------- 3) distance Gram kernel (64x64 tile, 64 threads, 8x8) -----
__global__ void dist_kernel() {
    __shared__ float As[16][68];
    __shared__ float Bs[16][68];
    const int b  = blockIdx.z;
    const int i0 = blockIdx.x * 64;
    const int j0 = blockIdx.y * 64;
    const float* Xb = g_xf + (size_t)b * NN * CC;
    const int tid = threadIdx.x;
    const int tx = tid & 7, ty = tid >> 3;

    float acc[8][8];
    #pragma unroll
    for (int i = 0; i < 8; i++)
        #pragma unroll
        for (int j = 0; j < 8; j++) acc[i][j] = 0.f;

    const int krow  = (tid & 3) * 4;   // k sub-offset this thread loads
    const int rbase = tid >> 2;        // row 0..15, plus p*16

    for (int k0 = 0; k0 < CC; k0 += 16) {
        #pragma unroll
        for (int p = 0; p < 4; p++) {
            int r = rbase + p * 16;
            float4 va = *(const float4*)(Xb + (size_t)(i0 + r)*CC + k0 + krow);
            As[krow+0][r] = va.x; As[krow+1][r] = va.y;
            As[krow+2][r] = va.z; As[krow+3][r] = va.w;
            float4 vb = *(const float4*)(Xb + (size_t)(j0 + r)*CC + k0 + krow);
            Bs[krow+0][r] = vb.x; Bs[krow+1][r] = vb.y;
            Bs[krow+2][r] = vb.z; Bs[krow+3][r] = vb.w;
        }
        __syncthreads();
        #pragma unroll
        for (int k = 0; k < 16; k++) {
            float a[8], bb[8];
            *(float4*)(a)    = *(const float4*)&As[k][ty*8];
            *(float4*)(a+4)  = *(const float4*)&As[k][ty*8+4];
            *(float4*)(bb)   = *(const float4*)&Bs[k][tx*8];
            *(float4*)(bb+4) = *(const float4*)&Bs[k][tx*8+4];
            #pragma unroll
            for (int i = 0; i < 8; i++)
                #pragma unroll
                for (int j = 0; j < 8; j++)
                    acc[i][j] = fmaf(a[i], bb[j], acc[i][j]);
        }
        __syncthreads();
    }

    const int bj = j0 + tx * 8;
    float4 x2a = *(const float4*)(g_x2 + b*NN + bj);
    float4 x2b = *(const float4*)(g_x2 + b*NN + bj + 4);
    #pragma unroll
    for (int i = 0; i < 8; i++) {
        int ii = i0 + ty * 8 + i;
        float* dst = g_s + ((size_t)b*NN + ii)*NN + bj;
        float4 o0, o1;
        o0.x = x2a.x - 2.f*acc[i][0]; o0.y = x2a.y - 2.f*acc[i][1];
        o0.z = x2a.z - 2.f*acc[i][2]; o0.w = x2a.w - 2.f*acc[i][3];
        o1.x = x2b.x - 2.f*acc[i][4]; o1.y = x2b.y - 2.f*acc[i][5];
        o1.z = x2b.z - 2.f*acc[i][6]; o1.w = x2b.w - 2.f*acc[i][7];
        *(float4*)(dst)     = o0;
        *(float4*)(dst + 4) = o1;
    }
}

// ---------------- 4) top-16 + max-relative + feature build ------------------
__global__ void topk_kernel() {
    __shared__ float sd[NN];             // 12.5 KB
    __shared__ float rv[8];
    __shared__ int   ri[8];
    __shared__ int   snbr[KNN];

    const int m = blockIdx.x;            // 0..MTOT-1
    const int b = m / NN, i = m % NN;
    const float* row = g_s + ((size_t)b*NN + i)*NN;
    const int tid = threadIdx.x;         // 256

    for (int j = tid; j < NN; j += 256) sd[j] = row[j];
    __syncthreads();

    for (int t = 0; t < KNN; t++) {
        float best = FLT_MAX; int bidx = NN;
        for (int j = tid; j < NN; j += 256) {
            float v = sd[j];
            if (v < best) { best = v; bidx = j; }
        }
        #pragma unroll
        for (int o = 16; o; o >>= 1) {
            float ov = __shfl_xor_sync(0xffffffffu, best, o);
            int   oi = __shfl_xor_sync(0xffffffffu, bidx, o);
            if (ov < best || (ov == best && oi < bidx)) { best = ov; bidx = oi; }
        }
        if ((tid & 31) == 0) { rv[tid >> 5] = best; ri[tid >> 5] = bidx; }
        __syncthreads();
        if (tid < 32) {
            best = (tid < 8) ? rv[tid] : FLT_MAX;
            bidx = (tid < 8) ? ri[tid] : NN;
            #pragma unroll
            for (int o = 4; o; o >>= 1) {
                float ov = __shfl_xor_sync(0xffffffffu, best, o);
                int   oi = __shfl_xor_sync(0xffffffffu, bidx, o);
                if (ov < best || (ov == best && oi < bidx)) { best = ov; bidx = oi; }
            }
            if (tid == 0) { snbr[t] = bidx; sd[bidx] = FLT_MAX; }
        }
        __syncthreads();
    }

    // gather neighbors, compute max-relative, write interleaved features
    const int c = tid;
    if (c < CC) {
        const float* Xb = g_xf + (size_t)b * NN * CC;
        float xi = Xb[(size_t)i*CC + c];
        float mx = -FLT_MAX;
        #pragma unroll
        for (int t = 0; t < KNN; t++)
            mx = fmaxf(mx, Xb[(size_t)snbr[t]*CC + c]);
        float* f = g_feat + (size_t)m * (2*CC);
        f[2*c]   = xi;
        f[2*c+1] = mx - xi;
    }
}

// ---------------- 5) GEMM: z[o][m] = feat[m]·w[o] + bias[o] -----------------
__global__ void gemm2_kernel(const float* __restrict__ w,
                             const float* __restrict__ bias) {
    __shared__ float As[16][68];   // feat  (k, m)
    __shared__ float Bs[16][68];   // w     (k, o)
    const int m0 = blockIdx.x * 64;
    const int o0 = blockIdx.y * 64;
    const int tid = threadIdx.x;
    const int tx = tid & 7, ty = tid >> 3;

    float acc[8][8];               // [mi][oi]
    #pragma unroll
    for (int i = 0; i < 8; i++)
        #pragma unroll
        for (int j = 0; j < 8; j++) acc[i][j] = 0.f;

    const int krow  = (tid & 3) * 4;
    const int rbase = tid >> 2;

    for (int k0 = 0; k0 < 2*CC; k0 += 16) {
        #pragma unroll
        for (int p = 0; p < 4; p++) {
            int r = rbase + p * 16;
            float4 va = *(const float4*)(g_feat + (size_t)(m0 + r)*(2*CC) + k0 + krow);
            As[krow+0][r] = va.x; As[krow+1][r] = va.y;
            As[krow+2][r] = va.z; As[krow+3][r] = va.w;
            float4 vb = *(const float4*)(w + (size_t)(o0 + r)*(2*CC) + k0 + krow);
            Bs[krow+0][r] = vb.x; Bs[krow+1][r] = vb.y;
            Bs[krow+2][r] = vb.z; Bs[krow+3][r] = vb.w;
        }
        __syncthreads();
        #pragma unroll
        for (int k = 0; k < 16; k++) {
            float a[8], bb[8];
            *(float4*)(a)    = *(const float4*)&As[k][ty*8];
            *(float4*)(a+4)  = *(const float4*)&As[k][ty*8+4];
            *(float4*)(bb)   = *(const float4*)&Bs[k][tx*8];
            *(float4*)(bb+4) = *(const float4*)&Bs[k][tx*8+4];
            #pragma unroll
            for (int i = 0; i < 8; i++)
                #pragma unroll
                for (int j = 0; j < 8; j++)
                    acc[i][j] = fmaf(a[i], bb[j], acc[i][j]);
        }
        __syncthreads();
    }

    #pragma unroll
    for (int j = 0; j < 8; j++) {
        int o = o0 + tx * 8 + j;
        float bv = bias[o];
        float* dst = g_z + (size_t)o * MTOT + m0 + ty * 8;
        float4 v0, v1;
        v0.x = acc[0][j] + bv; v0.y = acc[1][j] + bv;
        v0.z = acc[2][j] + bv; v0.w = acc[3][j] + bv;
        v1.x = acc[4][j] + bv; v1.y = acc[5][j] + bv;
        v1.z = acc[6][j] + bv; v1.w = acc[7][j] + bv;
        *(float4*)(dst)     = v0;
        *(float4*)(dst + 4) = v1;
    }
}

// ---------------- 6) per-channel mean/var -> scale/shift --------------------
__global__ void reduce_kernel(const float* __restrict__ gamma,
                              const float* __restrict__ beta) {
    __shared__ double ss[256], ss2[256];
    const int o = blockIdx.x;
    const float* p = g_z + (size_t)o * MTOT;
    double s = 0.0, s2 = 0.0;
    for (int m = threadIdx.x; m < MTOT; m += 256) {
        double v = (double)p[m];
        s += v; s2 += v * v;
    }
    ss[threadIdx.x] = s; ss2[threadIdx.x] = s2;
    __syncthreads();
    for (int stride = 128; stride; stride >>= 1) {
        if (threadIdx.x < stride) {
            ss[threadIdx.x]  += ss[threadIdx.x + stride];
            ss2[threadIdx.x] += ss2[threadIdx.x + stride];
        }
        __syncthreads();
    }
    if (threadIdx.x == 0) {
        double mean = ss[0] / (double)MTOT;
        double var  = ss2[0] / (double)MTOT - mean * mean;
        float rstd = rsqrtf((float)var + EPSV);
        float sc = gamma[o] * rstd;
        g_scale[o] = sc;
        g_shift[o] = beta[o] - (float)mean * sc;
    }
}

// ---------------- 7) BN + ReLU + write (B, OUT, H, W) -----------------------
__global__ void bn_kernel(float* __restrict__ out) {
    const int bo = blockIdx.x;          // b*OUTC + o
    const int b = bo / OUTC, o = bo % OUTC;
    const float sc = g_scale[o], sh = g_shift[o];
    const float* src = g_z + (size_t)o * MTOT + (size_t)b * NN;
    float* dst = out + (size_t)b * OUTC * NN + (size_t)o * NN;
    for (int n = threadIdx.x; n < NN; n += 256)
        dst[n] = fmaxf(fmaf(src[n], sc, sh), 0.f);
}

// ---------------- launch ----------------------------------------------------
extern "C" void kernel_launch(void* const* d_in, const int* in_sizes, int n_in,
                              void* d_out, int out_size) {
    const float* x     = (const float*)d_in[0];
    const float* w     = (const float*)d_in[1];
    const float* bias  = (const float*)d_in[2];
    const float* gamma = (const float*)d_in[3];
    const float* beta  = (const float*)d_in[4];
    float* out = (float*)d_out;

    transpose_kernel<<<dim3(98, 6, 8), dim3(32, 8)>>>(x);
    x2_kernel<<<NN, dim3(32, 8)>>>();
    dist_kernel<<<dim3(49, 49, 8), 64>>>();
    topk_kernel<<<MTOT, 256>>>();
    gemm2_kernel<<<dim3(MTOT/64, OUTC/64), 64>>>(w, bias);
    reduce_kernel<<<OUTC, 256>>>(gamma, beta);
    bn_kernel<<<BB * OUTC, 256>>>(out);
}

// round 2
// speedup vs baseline: 1.1558x; 1.1558x over previous
#include <cuda_runtime.h>
#include <math.h>
#include <float.h>

#define BB   8
#define CC   192
#define OUTC 384
#define NN   3136          // 56*56
#define KNN  16
#define MTOT (BB*NN)       // 25088
#define EPSV 1e-5f
#define TPB_TOPK 224       // 224 * 14 == 3136 exactly

// ---------------- scratch (device globals; no runtime allocation) ----------
__device__ float g_xf[(size_t)BB*NN*CC];          // (b, n, c)  19.3 MB
__device__ float g_x2[MTOT];                      // row squared norms
__device__ float g_s[(size_t)BB*NN*NN];           // s[b][i][j] = x2[j]-2*inner  315 MB
__device__ float g_feat[(size_t)MTOT*2*CC];       // interleaved (x, maxrel)  38.5 MB
__device__ float g_z[(size_t)OUTC*MTOT];          // z[o][m] pre-BN            38.5 MB
__device__ float g_scale[OUTC];
__device__ float g_shift[OUTC];

// ---------------- 1) transpose (B,C,N) -> (B,N,C) ---------------------------
__global__ void transpose_kernel(const float* __restrict__ x) {
    __shared__ float tile[32][33];
    int b  = blockIdx.z;
    int c0 = blockIdx.y * 32;
    int n0 = blockIdx.x * 32;
    int tx = threadIdx.x, ty = threadIdx.y;   // 32 x 8
    #pragma unroll
    for (int i = ty; i < 32; i += 8)
        tile[i][tx] = x[((size_t)b*CC + (c0+i))*NN + n0 + tx];
    __syncthreads();
    #pragma unroll
    for (int i = ty; i < 32; i += 8)
        g_xf[((size_t)b*NN + (n0+i))*CC + c0 + tx] = tile[tx][i];
}

// ---------------- 2) squared norms ------------------------------------------
__global__ void x2_kernel() {
    int row = blockIdx.x * 8 + threadIdx.y;   // MTOT = 3136*8 exact
    const float* p = g_xf + (size_t)row * CC;
    float s = 0.f;
    for (int c = threadIdx.x; c < CC; c += 32) { float v = p[c]; s += v*v; }
    #pragma unroll
    for (int o = 16; o; o >>= 1) s += __shfl_xor_sync(0xffffffffu, s, o);
    if (threadIdx.x == 0) g_x2[row] = s;
}

// ---------------- 3) distance Gram kernel (64x64 tile, 64 threads, 8x8) -----
__global__ void dist_kernel() {
    __shared__ float As[16][68];
    __shared__ float Bs[16][68];
    const int b  = blockIdx.z;
    const int i0 = blockIdx.x * 64;
    const int j0 = blockIdx.y * 64;
    const float* Xb = g_xf + (size_t)b * NN * CC;
    const int tid = threadIdx.x;
    const int tx = tid & 7, ty = tid >> 3;

    float acc[8][8];
    #pragma unroll
    for (int i = 0; i < 8; i++)
        #pragma unroll
        for (int j = 0; j < 8; j++) acc[i][j] = 0.f;

    const int krow  = (tid & 3) * 4;   // k sub-offset this thread loads
    const int rbase = tid >> 2;        // row 0..15, plus p*16

    for (int k0 = 0; k0 < CC; k0 += 16) {
        #pragma unroll
        for (int p = 0; p < 4; p++) {
            int r = rbase + p * 16;
            float4 va = *(const float4*)(Xb + (size_t)(i0 + r)*CC + k0 + krow);
            As[krow+0][r] = va.x; As[krow+1][r] = va.y;
            As[krow+2][r] = va.z; As[krow+3][r] = va.w;
            float4 vb = *(const float4*)(Xb + (size_t)(j0 + r)*CC + k0 + krow);
            Bs[krow+0][r] = vb.x; Bs[krow+1][r] = vb.y;
            Bs[krow+2][r] = vb.z; Bs[krow+3][r] = vb.w;
        }
        __syncthreads();
        #pragma unroll
        for (int k = 0; k < 16; k++) {
            float a[8], bb[8];
            *(float4*)(a)    = *(const float4*)&As[k][ty*8];
            *(float4*)(a+4)  = *(const float4*)&As[k][ty*8+4];
            *(float4*)(bb)   = *(const float4*)&Bs[k][tx*8];
            *(float4*)(bb+4) = *(const float4*)&Bs[k][tx*8+4];
            #pragma unroll
            for (int i = 0; i < 8; i++)
                #pragma unroll
                for (int j = 0; j < 8; j++)
                    acc[i][j] = fmaf(a[i], bb[j], acc[i][j]);
        }
        __syncthreads();
    }

    const int bj = j0 + tx * 8;
    float4 x2a = *(const float4*)(g_x2 + b*NN + bj);
    float4 x2b = *(const float4*)(g_x2 + b*NN + bj + 4);
    #pragma unroll
    for (int i = 0; i < 8; i++) {
        int ii = i0 + ty * 8 + i;
        float* dst = g_s + ((size_t)b*NN + ii)*NN + bj;
        float4 o0, o1;
        o0.x = x2a.x - 2.f*acc[i][0]; o0.y = x2a.y - 2.f*acc[i][1];
        o0.z = x2a.z - 2.f*acc[i][2]; o0.w = x2a.w - 2.f*acc[i][3];
        o1.x = x2b.x - 2.f*acc[i][4]; o1.y = x2b.y - 2.f*acc[i][5];
        o1.z = x2b.z - 2.f*acc[i][6]; o1.w = x2b.w - 2.f*acc[i][7];
        *(float4*)(dst)     = o0;
        *(float4*)(dst + 4) = o1;
    }
}

// ---------------- 4) top-16 + max-relative + feature build ------------------
// Monotone map: float -> uint32 preserving order for all finite floats.
__device__ __forceinline__ unsigned int f2sort(float f) {
    unsigned int u = __float_as_uint(f);
    return (u & 0x80000000u) ? ~u : (u | 0x80000000u);
}

__global__ void __launch_bounds__(TPB_TOPK) topk_kernel() {
    __shared__ unsigned long long cand[TPB_TOPK];
    __shared__ unsigned long long winner;
    __shared__ int snbr[KNN];

    const int m = blockIdx.x;            // 0..MTOT-1
    const int b = m / NN, i = m % NN;
    const float* row = g_s + ((size_t)b*NN + i)*NN;
    const int tid = threadIdx.x;

    // Load this thread's 14 strided elements into registers as sortable keys:
    // key = (sortable_value << 32) | index.  Ascending u64 order == ascending
    // (value, index) order, matching lax.top_k tie-breaking.
    unsigned long long key[14];
    #pragma unroll
    for (int t = 0; t < 14; t++) {
        int j = tid + TPB_TOPK * t;
        key[t] = ((unsigned long long)f2sort(row[j]) << 32) | (unsigned int)j;
    }
    unsigned long long lmin = key[0];
    #pragma unroll
    for (int t = 1; t < 14; t++) lmin = min(lmin, key[t]);
    cand[tid] = lmin;
    __syncthreads();

    for (int t = 0; t < KNN; t++) {
        if (tid < 32) {
            unsigned long long best = cand[tid];
            #pragma unroll
            for (int q = 1; q < 7; q++) best = min(best, cand[tid + 32*q]);
            #pragma unroll
            for (int o = 16; o; o >>= 1)
                best = min(best, __shfl_xor_sync(0xffffffffu, best, o));
            if (tid == 0) {
                winner = best;
                snbr[t] = (int)(best & 0xffffffffu);
            }
        }
        __syncthreads();
        int wj = (int)(winner & 0xffffffffu);
        if (tid == (wj % TPB_TOPK)) {
            int tt = wj / TPB_TOPK;
            #pragma unroll
            for (int q = 0; q < 14; q++)
                if (q == tt) key[q] = 0xffffffffffffffffULL;
            unsigned long long nl = key[0];
            #pragma unroll
            for (int q = 1; q < 14; q++) nl = min(nl, key[q]);
            cand[tid] = nl;
        }
        __syncthreads();
    }

    // gather neighbors, compute max-relative, write interleaved features
    const int c = tid;
    if (c < CC) {
        const float* Xb = g_xf + (size_t)b * NN * CC;
        float xi = Xb[(size_t)i*CC + c];
        float mx = -FLT_MAX;
        #pragma unroll
        for (int t = 0; t < KNN; t++)
            mx = fmaxf(mx, Xb[(size_t)snbr[t]*CC + c]);
        float* f = g_feat + (size_t)m * (2*CC);
        f[2*c]   = xi;
        f[2*c+1] = mx - xi;
    }
}

// ---------------- 5) GEMM: z[o][m] = feat[m]·w[o] + bias[o] -----------------
__global__ void gemm2_kernel(const float* __restrict__ w,
                             const float* __restrict__ bias) {
    __shared__ float As[16][68];   // feat  (k, m)
    __shared__ float Bs[16][68];   // w     (k, o)
    const int m0 = blockIdx.x * 64;
    const int o0 = blockIdx.y * 64;
    const int tid = threadIdx.x;
    const int tx = tid & 7, ty = tid >> 3;

    float acc[8][8];               // [mi][oi]
    #pragma unroll
    for (int i = 0; i < 8; i++)
        #pragma unroll
        for (int j = 0; j < 8; j++) acc[i][j] = 0.f;

    const int krow  = (tid & 3) * 4;
    const int rbase = tid >> 2;

    for (int k0 = 0; k0 < 2*CC; k0 += 16) {
        #pragma unroll
        for (int p = 0; p < 4; p++) {
            int r = rbase + p * 16;
            float4 va = *(const float4*)(g_feat + (size_t)(m0 + r)*(2*CC) + k0 + krow);
            As[krow+0][r] = va.x; As[krow+1][r] = va.y;
            As[krow+2][r] = va.z; As[krow+3][r] = va.w;
            float4 vb = *(const float4*)(w + (size_t)(o0 + r)*(2*CC) + k0 + krow);
            Bs[krow+0][r] = vb.x; Bs[krow+1][r] = vb.y;
            Bs[krow+2][r] = vb.z; Bs[krow+3][r] = vb.w;
        }
        __syncthreads();
        #pragma unroll
        for (int k = 0; k < 16; k++) {
            float a[8], bb[8];
            *(float4*)(a)    = *(const float4*)&As[k][ty*8];
            *(float4*)(a+4)  = *(const float4*)&As[k][ty*8+4];
            *(float4*)(bb)   = *(const float4*)&Bs[k][tx*8];
            *(float4*)(bb+4) = *(const float4*)&Bs[k][tx*8+4];
            #pragma unroll
            for (int i = 0; i < 8; i++)
                #pragma unroll
                for (int j = 0; j < 8; j++)
                    acc[i][j] = fmaf(a[i], bb[j], acc[i][j]);
        }
        __syncthreads();
    }

    #pragma unroll
    for (int j = 0; j < 8; j++) {
        int o = o0 + tx * 8 + j;
        float bv = bias[o];
        float* dst = g_z + (size_t)o * MTOT + m0 + ty * 8;
        float4 v0, v1;
        v0.x = acc[0][j] + bv; v0.y = acc[1][j] + bv;
        v0.z = acc[2][j] + bv; v0.w = acc[3][j] + bv;
        v1.x = acc[4][j] + bv; v1.y = acc[5][j] + bv;
        v1.z = acc[6][j] + bv; v1.w = acc[7][j] + bv;
        *(float4*)(dst)     = v0;
        *(float4*)(dst + 4) = v1;
    }
}

// ---------------- 6) per-channel mean/var -> scale/shift --------------------
__global__ void reduce_kernel(const float* __restrict__ gamma,
                              const float* __restrict__ beta) {
    __shared__ double ss[256], ss2[256];
    const int o = blockIdx.x;
    const float* p = g_z + (size_t)o * MTOT;
    double s = 0.0, s2 = 0.0;
    for (int m = threadIdx.x; m < MTOT; m += 256) {
        double v = (double)p[m];
        s += v; s2 += v * v;
    }
    ss[threadIdx.x] = s; ss2[threadIdx.x] = s2;
    __syncthreads();
    for (int stride = 128; stride; stride >>= 1) {
        if (threadIdx.x < stride) {
            ss[threadIdx.x]  += ss[threadIdx.x + stride];
            ss2[threadIdx.x] += ss2[threadIdx.x + stride];
        }
        __syncthreads();
    }
    if (threadIdx.x == 0) {
        double mean = ss[0] / (double)MTOT;
        double var  = ss2[0] / (double)MTOT - mean * mean;
        float rstd = rsqrtf((float)var + EPSV);
        float sc = gamma[o] * rstd;
        g_scale[o] = sc;
        g_shift[o] = beta[o] - (float)mean * sc;
    }
}

// ---------------- 7) BN + ReLU + write (B, OUT, H, W) -----------------------
__global__ void bn_kernel(float* __restrict__ out) {
    const int bo = blockIdx.x;          // b*OUTC + o
    const int b = bo / OUTC, o = bo % OUTC;
    const float sc = g_scale[o], sh = g_shift[o];
    const float* src = g_z + (size_t)o * MTOT + (size_t)b * NN;
    float* dst = out + (size_t)b * OUTC * NN + (size_t)o * NN;
    for (int n = threadIdx.x; n < NN; n += 256)
        dst[n] = fmaxf(fmaf(src[n], sc, sh), 0.f);
}

// ---------------- launch ----------------------------------------------------
extern "C" void kernel_launch(void* const* d_in, const int* in_sizes, int n_in,
                              void* d_out, int out_size) {
    const float* x     = (const float*)d_in[0];
    const float* w     = (const float*)d_in[1];
    const float* bias  = (const float*)d_in[2];
    const float* gamma = (const float*)d_in[3];
    const float* beta  = (const float*)d_in[4];
    float* out = (float*)d_out;

    transpose_kernel<<<dim3(98, 6, 8), dim3(32, 8)>>>(x);
    x2_kernel<<<NN, dim3(32, 8)>>>();
    dist_kernel<<<dim3(49, 49, 8), 64>>>();
    topk_kernel<<<MTOT, TPB_TOPK>>>();
    gemm2_kernel<<<dim3(MTOT/64, OUTC/64), 64>>>(w, bias);
    reduce_kernel<<<OUTC, 256>>>(gamma, beta);
    bn_kernel<<<BB * OUTC, 256>>>(out);
}